// round 1
// baseline (speedup 1.0000x reference)
#include <cuda_runtime.h>
#include <math.h>

#define BATCH   256
#define JN      10
#define ICAPS   1152
#define DN      16
#define EN      8
#define JD      160      // JN*DN

// -------- scratch (static device allocations are the sanctioned path) ------
__device__ float g_uhat[(size_t)BATCH * ICAPS * JD];   // [b][i][j*16+d], ~189MB
__device__ float g_s0[BATCH * JD];
__device__ float g_v0[BATCH * JD];
__device__ float g_v1[BATCH * JD];

// -------- K0: zero the s0 accumulator ----------------------------------
__global__ void k_zero() {
    int t = blockIdx.x * blockDim.x + threadIdx.x;
    if (t < BATCH * JD) g_s0[t] = 0.0f;
}

// -------- K1: u_hat = W @ x, fused partial s0 (uniform c = 1/10, factor applied later)
// grid (1152/16, 256/64), 320 threads: t%160 = (j*16+d), t/160 = b-half
__global__ __launch_bounds__(320) void k_uhat(const float* __restrict__ x,
                                              const float* __restrict__ W) {
    __shared__ float4 xs4[64 * 32];   // x[b0+b][i0+i][e]: 64 b * 16 i * 8 e = 2048 float4
    const int i0 = blockIdx.x * 16;
    const int b0 = blockIdx.y * 64;
    const int t  = threadIdx.x;

    const float4* xg = (const float4*)x;   // x is [256][1152][8] -> 2304 float4 per b
    for (int f = t; f < 2048; f += 320) {
        int b = f >> 5, q = f & 31;
        xs4[f] = xg[(size_t)(b0 + b) * 2304 + (size_t)i0 * 2 + q];
    }
    __syncthreads();

    const int jd = t % 160;
    const int g  = t / 160;          // 0/1 -> which 32-b half
    const int j  = jd >> 4, d = jd & 15;
    // W[j][i][d][e] offset = j*147456 + i*128 + d*8 (floats); 32B-aligned for float4
    const float4* Wg = (const float4*)(W + (size_t)j * 147456 + (size_t)d * 8);

    for (int bt = 0; bt < 4; bt++) {
        const int bbase = g * 32 + bt * 8;
        float acc[8] = {0.f,0.f,0.f,0.f,0.f,0.f,0.f,0.f};
        for (int ii = 0; ii < 16; ii++) {
            const int i = i0 + ii;
            const float4 w0 = Wg[(size_t)i * 32];
            const float4 w1 = Wg[(size_t)i * 32 + 1];
            #pragma unroll
            for (int bb = 0; bb < 8; bb++) {
                const int b = bbase + bb;
                const float4 xa = xs4[b * 32 + ii * 2];
                const float4 xb = xs4[b * 32 + ii * 2 + 1];
                float u = w0.x*xa.x + w0.y*xa.y + w0.z*xa.z + w0.w*xa.w
                        + w1.x*xb.x + w1.y*xb.y + w1.z*xb.z + w1.w*xb.w;
                g_uhat[((size_t)(b0 + b) * ICAPS + i) * JD + jd] = u;
                acc[bb] += u;
            }
        }
        #pragma unroll
        for (int bb = 0; bb < 8; bb++)
            atomicAdd(&g_s0[(b0 + bbase + bb) * JD + jd], acc[bb]);
    }
}

// -------- K2: v0 = squash(0.1 * s0) ------------------------------------
__global__ void k_v0() {   // grid 256, 160 threads
    __shared__ float ss[JD];
    __shared__ float sc[JN];
    const int b = blockIdx.x, t = threadIdx.x;
    ss[t] = 0.1f * g_s0[b * JD + t];
    __syncthreads();
    if (t < JN) {
        float sq = 0.f;
        #pragma unroll
        for (int d = 0; d < DN; d++) { float v = ss[t * DN + d]; sq += v * v; }
        sc[t] = (sq / (1.0f + sq)) * rsqrtf(sq + 1e-7f);
    }
    __syncthreads();
    g_v0[b * JD + t] = ss[t] * sc[t >> 4];
}

// -------- K3/K4: fused routing pass ------------------------------------
// cc[j,i] = u_hat[j,i,:] . vsum[j,:]  (vsum = v0 [+ v1]), softmax over j,
// s[j,d] = sum_i c[j,i] u_hat[j,i,d], v = squash(s).
// addB==0: vsum=v0, result -> g_v1.   addB==1: vsum=v0+v1, result -> vout.
#define CH 64
__global__ __launch_bounds__(256) void k_route(int addB, float* __restrict__ vout) {
    __shared__ float su[CH * 161];    // chunk of u_hat, pad stride 161 (conflict-free)
    __shared__ float cbuf[CH * JN];
    __shared__ float vs[JD];
    __shared__ float ss[JD];
    __shared__ float sc[JN];

    const int b = blockIdx.x, t = threadIdx.x;
    if (t < JD) vs[t] = addB ? (g_v0[b * JD + t] + g_v1[b * JD + t])
                             : g_v0[b * JD + t];
    const float* ub = g_uhat + (size_t)b * ICAPS * JD;
    const int j_ = t >> 4;            // for t<160 phase-B mapping (j, d)
    float sa0 = 0.f, sa1 = 0.f;       // register s accumulators across chunks
    __syncthreads();

    for (int c = 0; c < ICAPS / CH; c++) {
        // ---- load chunk: contiguous CH*160 floats -> padded SMEM ----
        const float4* src = (const float4*)(ub + (size_t)c * CH * JD);
        for (int f = t; f < CH * 40; f += 256) {
            float4 v4 = src[f];
            int i = f / 40, q = f % 40;
            float* dst = &su[i * 161 + q * 4];
            dst[0] = v4.x; dst[1] = v4.y; dst[2] = v4.z; dst[3] = v4.w;
        }
        __syncthreads();

        // ---- phase A: one thread per input capsule ----
        if (t < CH) {
            const float* u = &su[t * 161];
            float cc[JN];
            #pragma unroll
            for (int j = 0; j < JN; j++) {
                float a = 0.f;
                #pragma unroll
                for (int d = 0; d < DN; d++) a = fmaf(u[j * DN + d], vs[j * DN + d], a);
                cc[j] = a;
            }
            float m = cc[0];
            #pragma unroll
            for (int j = 1; j < JN; j++) m = fmaxf(m, cc[j]);
            float sum = 0.f;
            #pragma unroll
            for (int j = 0; j < JN; j++) { cc[j] = __expf(cc[j] - m); sum += cc[j]; }
            const float inv = __fdividef(1.0f, sum);
            #pragma unroll
            for (int j = 0; j < JN; j++) cbuf[t * JN + j] = cc[j] * inv;
        }
        __syncthreads();

        // ---- phase B: 160 threads accumulate s[j,d] over the chunk ----
        if (t < JD) {
            #pragma unroll 4
            for (int i = 0; i < CH; i += 2) {
                sa0 = fmaf(cbuf[i * JN + j_],       su[i * 161 + t],       sa0);
                sa1 = fmaf(cbuf[(i + 1) * JN + j_], su[(i + 1) * 161 + t], sa1);
            }
        }
        __syncthreads();
    }

    if (t < JD) ss[t] = sa0 + sa1;
    __syncthreads();
    if (t < JN) {
        float sq = 0.f;
        #pragma unroll
        for (int d = 0; d < DN; d++) { float v = ss[t * DN + d]; sq += v * v; }
        sc[t] = (sq / (1.0f + sq)) * rsqrtf(sq + 1e-7f);
    }
    __syncthreads();
    if (t < JD) {
        float v = ss[t] * sc[j_];
        if (addB) vout[b * JD + t] = v;
        else      g_v1[b * JD + t] = v;
    }
}

// -------- launch --------------------------------------------------------
extern "C" void kernel_launch(void* const* d_in, const int* in_sizes, int n_in,
                              void* d_out, int out_size) {
    const float* x = (const float*)d_in[0];   // [256,1152,8]
    const float* W = (const float*)d_in[1];   // [10,1152,16,8]
    float* out = (float*)d_out;               // [256,10,16]

    k_zero<<<160, 256>>>();
    k_uhat<<<dim3(ICAPS / 16, BATCH / 64), 320>>>(x, W);
    k_v0<<<BATCH, JD>>>();
    k_route<<<BATCH, 256>>>(0, nullptr);   // round-1 pass -> v1
    k_route<<<BATCH, 256>>>(1, out);       // round-2 pass -> output
}

// round 2
// speedup vs baseline: 1.5627x; 1.5627x over previous
#include <cuda_runtime.h>
#include <cuda_fp16.h>
#include <math.h>

#define BATCH   256
#define JN      10
#define ICAPS   1152
#define DN      16
#define JD      160          // JN*DN
#define CH      64           // i-chunk for routing
#define NCHUNK  (ICAPS/CH)   // 18
#define PADJD   168          // padded row (halves): 336B, 16B-aligned

// -------- scratch ------------------------------------------------------
__device__ __half g_uhat[(size_t)BATCH * ICAPS * JD];   // ~94.4 MB (fits L2)
__device__ float  g_s0[BATCH * JD];

// -------- cp.async helpers ---------------------------------------------
__device__ __forceinline__ void cp16(void* sdst, const void* gsrc) {
    unsigned s = (unsigned)__cvta_generic_to_shared(sdst);
    asm volatile("cp.async.cg.shared.global [%0], [%1], 16;\n" :: "r"(s), "l"(gsrc));
}
__device__ __forceinline__ void cp_commit() { asm volatile("cp.async.commit_group;\n"); }
template<int N> __device__ __forceinline__ void cp_wait() {
    asm volatile("cp.async.wait_group %0;\n" :: "n"(N));
}

// -------- K0: zero s0 ---------------------------------------------------
__global__ void k_zero() {
    int t = blockIdx.x * blockDim.x + threadIdx.x;
    if (t < BATCH * JD) g_s0[t] = 0.0f;
}

// -------- K1: u_hat = W @ x (fp16 out), fused partial s0 ----------------
// grid (1152/16, 256/64), 320 threads: t%160 = (j*16+d), t/160 = b-half
__global__ __launch_bounds__(320) void k_uhat(const float* __restrict__ x,
                                              const float* __restrict__ W) {
    __shared__ float4 xs4[64 * 32];   // 64 b * 16 i * 2 float4
    const int i0 = blockIdx.x * 16;
    const int b0 = blockIdx.y * 64;
    const int t  = threadIdx.x;

    const float4* xg = (const float4*)x;   // [256][1152][8] -> 2304 float4 per b
    for (int f = t; f < 2048; f += 320) {
        int b = f >> 5, q = f & 31;
        xs4[f] = xg[(size_t)(b0 + b) * 2304 + (size_t)i0 * 2 + q];
    }
    __syncthreads();

    const int jd = t % 160;
    const int g  = t / 160;
    const int j  = jd >> 4, d = jd & 15;
    const float4* Wg = (const float4*)(W + (size_t)j * 147456 + (size_t)d * 8);

    for (int bt = 0; bt < 4; bt++) {
        const int bbase = g * 32 + bt * 8;
        float acc[8] = {0.f,0.f,0.f,0.f,0.f,0.f,0.f,0.f};
        for (int ii = 0; ii < 16; ii++) {
            const int i = i0 + ii;
            const float4 w0 = Wg[(size_t)i * 32];
            const float4 w1 = Wg[(size_t)i * 32 + 1];
            #pragma unroll
            for (int bb = 0; bb < 8; bb++) {
                const int b = bbase + bb;
                const float4 xa = xs4[b * 32 + ii * 2];
                const float4 xb = xs4[b * 32 + ii * 2 + 1];
                float u = w0.x*xa.x + w0.y*xa.y + w0.z*xa.z + w0.w*xa.w
                        + w1.x*xb.x + w1.y*xb.y + w1.z*xb.z + w1.w*xb.w;
                g_uhat[((size_t)(b0 + b) * ICAPS + i) * JD + jd] = __float2half_rn(u);
                acc[bb] += u;
            }
        }
        #pragma unroll
        for (int bb = 0; bb < 8; bb++)
            atomicAdd(&g_s0[(b0 + bbase + bb) * JD + jd], acc[bb]);
    }
}

// -------- K2: fused routing (v0 squash + both passes) -------------------
// One CTA per b, 320 threads. Double-buffered cp.async chunk pipeline.
__global__ __launch_bounds__(320) void k_route(float* __restrict__ out) {
    __shared__ __half su[2][CH * PADJD];   // 2 * 21504 B = 43 KB
    __shared__ float  cc[CH * JN];         // logits then coupling coeffs
    __shared__ float  vs[JD];              // running vsum (v0 [+ v1])
    __shared__ float  red[JD];             // reductions
    __shared__ float  sc[JN];              // squash scales

    const int b = blockIdx.x, t = threadIdx.x;
    const __half* ub = g_uhat + (size_t)b * ICAPS * JD;

    // ---- v0 = squash(0.1 * s0) ----
    if (t < JD) red[t] = 0.1f * g_s0[b * JD + t];
    __syncthreads();
    if (t < JN) {
        float sq = 0.f;
        #pragma unroll
        for (int d = 0; d < DN; d++) { float v = red[t * DN + d]; sq += v * v; }
        sc[t] = (sq / (1.0f + sq)) * rsqrtf(sq + 1e-7f);
    }
    __syncthreads();
    if (t < JD) vs[t] = red[t] * sc[t >> 4];
    // (sync before first use is provided by the post-wait sync below)

    const int jd_ = (t < JD) ? t : (t - JD);   // phase-B lane
    const int h_  = (t < JD) ? 0 : 1;
    const int jB  = jd_ >> 4;

    for (int p = 0; p < 2; p++) {
        float sa = 0.f;

        // prefetch chunk 0
        for (int f = t; f < CH * 20; f += 320) {
            int i = f / 20, q = f % 20;
            cp16(&su[0][i * PADJD + q * 8], ub + (size_t)i * JD + q * 8);
        }
        cp_commit();

        for (int c = 0; c < NCHUNK; c++) {
            if (c + 1 < NCHUNK) {
                const __half* src = ub + (size_t)(c + 1) * CH * JD;
                __half* dst = su[(c + 1) & 1];
                for (int f = t; f < CH * 20; f += 320) {
                    int i = f / 20, q = f % 20;
                    cp16(&dst[i * PADJD + q * 8], src + (size_t)i * JD + q * 8);
                }
                cp_commit();
                cp_wait<1>();
            } else {
                cp_wait<0>();
            }
            __syncthreads();
            const __half* u = su[c & 1];

            // ---- phase A: 640 (i,j) dot tasks over 320 threads ----
            #pragma unroll
            for (int k = 0; k < 2; k++) {
                int task = t + k * 320;
                int i = (task * 205) >> 11;          // exact floor(task/10) for task<640
                int j = task - i * 10;
                const __half2* up = (const __half2*)(u + i * PADJD + j * DN);
                const float* v = vs + j * DN;
                float a = 0.f;
                #pragma unroll
                for (int d2 = 0; d2 < 8; d2++) {
                    float2 uf = __half22float2(up[d2]);
                    a = fmaf(uf.x, v[2 * d2],     a);
                    a = fmaf(uf.y, v[2 * d2 + 1], a);
                }
                cc[i * JN + j] = a;
            }
            __syncthreads();

            // ---- softmax over j, per input capsule ----
            if (t < CH) {
                float l[JN];
                #pragma unroll
                for (int j = 0; j < JN; j++) l[j] = cc[t * JN + j];
                float m = l[0];
                #pragma unroll
                for (int j = 1; j < JN; j++) m = fmaxf(m, l[j]);
                float sum = 0.f;
                #pragma unroll
                for (int j = 0; j < JN; j++) { l[j] = __expf(l[j] - m); sum += l[j]; }
                float inv = __fdividef(1.0f, sum);
                #pragma unroll
                for (int j = 0; j < JN; j++) cc[t * JN + j] = l[j] * inv;
            }
            __syncthreads();

            // ---- phase B: s[jd] += sum_i c[i,j] * u[i,jd]; 2 i-halves ----
            {
                const __half* up = u + jd_ + h_ * 32 * PADJD;
                const float* cp = cc + h_ * 32 * JN + jB;
                #pragma unroll 8
                for (int i = 0; i < 32; i++)
                    sa = fmaf(cp[i * JN], __half2float(up[i * PADJD]), sa);
            }
            __syncthreads();   // protect su / cc reuse
        }

        // ---- combine halves, squash ----
        if (t < JD) red[t] = sa;
        __syncthreads();
        if (t >= JD) red[jd_] += sa;
        __syncthreads();
        if (t < JN) {
            float sq = 0.f;
            #pragma unroll
            for (int d = 0; d < DN; d++) { float v = red[t * DN + d]; sq += v * v; }
            sc[t] = (sq / (1.0f + sq)) * rsqrtf(sq + 1e-7f);
        }
        __syncthreads();
        if (t < JD) {
            float v1 = red[t] * sc[t >> 4];
            if (p == 0) vs[t] += v1;              // vsum = v0 + v1
            else        out[b * JD + t] = v1;     // final v
        }
        __syncthreads();
    }
}

// -------- launch --------------------------------------------------------
extern "C" void kernel_launch(void* const* d_in, const int* in_sizes, int n_in,
                              void* d_out, int out_size) {
    const float* x = (const float*)d_in[0];   // [256,1152,8]
    const float* W = (const float*)d_in[1];   // [10,1152,16,8]
    float* out = (float*)d_out;               // [256,10,16]

    k_zero<<<160, 256>>>();
    k_uhat<<<dim3(ICAPS / 16, BATCH / 64), 320>>>(x, W);
    k_route<<<BATCH, 320>>>(out);
}

// round 3
// speedup vs baseline: 1.6568x; 1.0602x over previous
#include <cuda_runtime.h>
#include <cuda_fp16.h>
#include <math.h>

#define BATCH   256
#define JN      10
#define ICAPS   1152
#define DN      16
#define JD      160          // JN*DN
#define CH      64           // i-chunk per routing CTA
#define NCHUNK  (ICAPS/CH)   // 18
#define PADJD   168          // padded SMEM row in halves (336B)

// -------- scratch ------------------------------------------------------
__device__ __half g_uhat[(size_t)BATCH * ICAPS * JD];   // ~94.4 MB
__device__ float  g_s0[BATCH * JD];     // round-0 uniform-c accumulator
__device__ float  g_sacc[BATCH * JD];   // per-round s accumulator
__device__ float  g_vs[BATCH * JD];     // running vsum (v0 [+ v1])

// -------- cp.async helpers ---------------------------------------------
__device__ __forceinline__ void cp16(void* sdst, const void* gsrc) {
    unsigned s = (unsigned)__cvta_generic_to_shared(sdst);
    asm volatile("cp.async.cg.shared.global [%0], [%1], 16;\n" :: "r"(s), "l"(gsrc));
}
__device__ __forceinline__ void cp_commit() { asm volatile("cp.async.commit_group;\n"); }
template<int N> __device__ __forceinline__ void cp_wait() {
    asm volatile("cp.async.wait_group %0;\n" :: "n"(N));
}

// -------- K1: u_hat = W @ x (fp16, half2 stores), fused partial s0 ------
// grid (72, 4), 320 threads. t%80 = jd2 (j*8 + dpair), t/80 = b 16-group.
__global__ __launch_bounds__(320) void k_uhat(const float* __restrict__ x,
                                              const float* __restrict__ W) {
    __shared__ float4 xs4[64 * 32];   // 64 b * 16 i * 2 float4
    const int i0 = blockIdx.x * 16;
    const int b0 = blockIdx.y * 64;
    const int t  = threadIdx.x;

    const float4* xg = (const float4*)x;   // [256][1152][8] -> 2304 float4/b
    for (int f = t; f < 2048; f += 320) {
        int b = f >> 5, q = f & 31;
        xs4[f] = xg[(size_t)(b0 + b) * 2304 + (size_t)i0 * 2 + q];
    }
    __syncthreads();

    const int jd2 = t % 80;         // j*8 + dp
    const int seg = t / 80;         // 0..3
    const int j   = jd2 >> 3, dp = jd2 & 7, d0 = dp * 2;
    // float4 index into W: j*36864 + i*32 + d*2
    const float4* Wg = (const float4*)W + (size_t)j * 36864 + d0 * 2;
    __half2* uh2 = (__half2*)g_uhat;

    for (int bt = 0; bt < 2; bt++) {
        const int bbase = seg * 16 + bt * 8;
        float acc0[8] = {0,0,0,0,0,0,0,0};
        float acc1[8] = {0,0,0,0,0,0,0,0};
        for (int ii = 0; ii < 16; ii++) {
            const int i = i0 + ii;
            const float4 w00 = Wg[(size_t)i * 32];
            const float4 w01 = Wg[(size_t)i * 32 + 1];
            const float4 w10 = Wg[(size_t)i * 32 + 2];
            const float4 w11 = Wg[(size_t)i * 32 + 3];
            #pragma unroll
            for (int bb = 0; bb < 8; bb++) {
                const int b = bbase + bb;
                const float4 xa = xs4[b * 32 + ii * 2];
                const float4 xb = xs4[b * 32 + ii * 2 + 1];
                float u0 = w00.x*xa.x + w00.y*xa.y + w00.z*xa.z + w00.w*xa.w
                         + w01.x*xb.x + w01.y*xb.y + w01.z*xb.z + w01.w*xb.w;
                float u1 = w10.x*xa.x + w10.y*xa.y + w10.z*xa.z + w10.w*xa.w
                         + w11.x*xb.x + w11.y*xb.y + w11.z*xb.z + w11.w*xb.w;
                uh2[((size_t)(b0 + b) * ICAPS + i) * 80 + jd2] =
                    __floats2half2_rn(u0, u1);
                acc0[bb] += u0;
                acc1[bb] += u1;
            }
        }
        #pragma unroll
        for (int bb = 0; bb < 8; bb++) {
            float* s = &g_s0[(b0 + bbase + bb) * JD + jd2 * 2];
            atomicAdd(s,     acc0[bb]);
            atomicAdd(s + 1, acc1[bb]);
        }
    }
}

// -------- k_sq: squash + bookkeeping ------------------------------------
// mode 0: v0 = squash(0.1*s0) -> g_vs;            zero g_sacc
// mode 1: v1 = squash(sacc)   -> g_vs += v1;      zero g_sacc
// mode 2: v  = squash(sacc)   -> out
__global__ void k_sq(int mode, float* __restrict__ out) {
    __shared__ float red[JD];
    __shared__ float sc[JN];
    const int b = blockIdx.x, t = threadIdx.x;
    float s = (mode == 0) ? 0.1f * g_s0[b * JD + t] : g_sacc[b * JD + t];
    red[t] = s;
    __syncthreads();
    if (t < JN) {
        float sq = 0.f;
        #pragma unroll
        for (int d = 0; d < DN; d++) { float v = red[t * DN + d]; sq += v * v; }
        sc[t] = (sq / (1.0f + sq)) * rsqrtf(sq + 1e-7f);
    }
    __syncthreads();
    float v = red[t] * sc[t >> 4];
    if (mode == 0)      { g_vs[b * JD + t] = v;  g_sacc[b * JD + t] = 0.f; }
    else if (mode == 1) { g_vs[b * JD + t] += v; g_sacc[b * JD + t] = 0.f; }
    else                { out[b * JD + t] = v; }
}

// -------- k_pass: one routing pass over a 64-i chunk --------------------
// grid (18, 256), 320 threads. cc -> softmax_j -> partial s -> atomicAdd.
__global__ __launch_bounds__(320) void k_pass() {
    __shared__ __half su[CH * PADJD];   // 21504 B
    __shared__ float  cc[CH * JN];
    __shared__ float  vs[JD];

    const int b = blockIdx.y, c = blockIdx.x, t = threadIdx.x;
    const __half* ub = g_uhat + ((size_t)b * ICAPS + (size_t)c * CH) * JD;

    if (t < JD) vs[t] = g_vs[b * JD + t];

    // load chunk: 64 rows x 160 halves (320B) = 20 x 16B per row
    for (int f = t; f < CH * 20; f += 320) {
        int i = f / 20, q = f % 20;
        cp16(&su[i * PADJD + q * 8], ub + (size_t)i * JD + q * 8);
    }
    cp_commit();
    cp_wait<0>();
    __syncthreads();

    // ---- phase A: 640 (i,j) dot tasks over 320 threads ----
    #pragma unroll
    for (int k = 0; k < 2; k++) {
        int task = t + k * 320;
        int i = (task * 205) >> 11;          // floor(task/10), task<640
        int j = task - i * 10;
        const __half2* up = (const __half2*)(su + i * PADJD + j * DN);
        const float* v = vs + j * DN;
        float a = 0.f;
        #pragma unroll
        for (int d2 = 0; d2 < 8; d2++) {
            float2 uf = __half22float2(up[d2]);
            a = fmaf(uf.x, v[2 * d2],     a);
            a = fmaf(uf.y, v[2 * d2 + 1], a);
        }
        cc[i * JN + j] = a;
    }
    __syncthreads();

    // ---- softmax over j per input capsule ----
    if (t < CH) {
        float l[JN];
        #pragma unroll
        for (int j = 0; j < JN; j++) l[j] = cc[t * JN + j];
        float m = l[0];
        #pragma unroll
        for (int j = 1; j < JN; j++) m = fmaxf(m, l[j]);
        float sum = 0.f;
        #pragma unroll
        for (int j = 0; j < JN; j++) { l[j] = __expf(l[j] - m); sum += l[j]; }
        float inv = __fdividef(1.0f, sum);
        #pragma unroll
        for (int j = 0; j < JN; j++) cc[t * JN + j] = l[j] * inv;
    }
    __syncthreads();

    // ---- phase B: partial s[jd] over 32 i's per half, then atomicAdd ----
    {
        const int jd = (t < JD) ? t : (t - JD);
        const int h  = (t < JD) ? 0 : 1;
        const int jB = jd >> 4;
        const __half* up = su + jd + h * 32 * PADJD;
        const float* cp = cc + h * 32 * JN + jB;
        float sa = 0.f;
        #pragma unroll 8
        for (int i = 0; i < 32; i++)
            sa = fmaf(cp[i * JN], __half2float(up[i * PADJD]), sa);
        atomicAdd(&g_sacc[b * JD + jd], sa);
    }
}

// -------- launch --------------------------------------------------------
extern "C" void kernel_launch(void* const* d_in, const int* in_sizes, int n_in,
                              void* d_out, int out_size) {
    const float* x = (const float*)d_in[0];   // [256,1152,8]
    const float* W = (const float*)d_in[1];   // [10,1152,16,8]
    float* out = (float*)d_out;               // [256,10,16]

    void* s0_ptr = nullptr;
    cudaGetSymbolAddress(&s0_ptr, g_s0);
    cudaMemsetAsync(s0_ptr, 0, BATCH * JD * sizeof(float));

    k_uhat<<<dim3(ICAPS / 16, BATCH / 64), 320>>>(x, W);
    k_sq<<<BATCH, JD>>>(0, nullptr);          // v0 -> g_vs, zero sacc
    k_pass<<<dim3(NCHUNK, BATCH), 320>>>();   // round-1 logits+softmax+s
    k_sq<<<BATCH, JD>>>(1, nullptr);          // vsum = v0+v1, zero sacc
    k_pass<<<dim3(NCHUNK, BATCH), 320>>>();   // round-2
    k_sq<<<BATCH, JD>>>(2, out);              // final v
}

// round 4
// speedup vs baseline: 1.6736x; 1.0101x over previous
#include <cuda_runtime.h>
#include <cuda_fp16.h>
#include <math.h>

#define BATCH   256
#define JN      10
#define ICAPS   1152
#define DN      16
#define JD      160          // JN*DN
#define CH      64           // i-chunk
#define MCH     3            // chunks per pass CTA
#define GRIDX   (ICAPS/(CH*MCH))   // 6
#define PADJD   168          // padded SMEM row in halves (336B)

// -------- scratch ------------------------------------------------------
__device__ __half g_uhat[(size_t)BATCH * ICAPS * JD];   // ~94.4 MB
__device__ float  g_acc[3 * BATCH * JD];   // [0]=s0raw, [1]=sacc1, [2]=sacc2

// -------- f32x2 / misc helpers -----------------------------------------
typedef unsigned long long u64t;
__device__ __forceinline__ u64t pack2(float x, float y) {
    u64t r; asm("mov.b64 %0, {%1, %2};" : "=l"(r) : "f"(x), "f"(y)); return r;
}
__device__ __forceinline__ void unpack2(u64t v, float& x, float& y) {
    asm("mov.b64 {%0, %1}, %2;" : "=f"(x), "=f"(y) : "l"(v));
}
__device__ __forceinline__ u64t fma2(u64t a, u64t b, u64t c) {
    u64t d; asm("fma.rn.f32x2 %0, %1, %2, %3;" : "=l"(d) : "l"(a), "l"(b), "l"(c));
    return d;
}
__device__ __forceinline__ u64t addf2(u64t a, u64t b) {
    u64t d; asm("add.rn.f32x2 %0, %1, %2;" : "=l"(d) : "l"(a), "l"(b)); return d;
}
__device__ __forceinline__ void cp16(void* sdst, const void* gsrc) {
    unsigned s = (unsigned)__cvta_generic_to_shared(sdst);
    asm volatile("cp.async.cg.shared.global [%0], [%1], 16;\n" :: "r"(s), "l"(gsrc));
}
__device__ __forceinline__ void cp_commit() { asm volatile("cp.async.commit_group;\n"); }
template<int N> __device__ __forceinline__ void cp_wait() {
    asm volatile("cp.async.wait_group %0;\n" :: "n"(N));
}

// -------- K1: u_hat = W @ x (fp16 out) via f32x2, fused partial s0 ------
// grid (72, 4), 320 threads: t%80 = jd2 (j*8+dp), t/80 = seg (16 b each)
__global__ __launch_bounds__(320, 2) void k_uhat(const float* __restrict__ x,
                                                 const float* __restrict__ W) {
    // xs[i][e2][b2][el*2+bl] — interleaved so (e,b-pair) reads are ulonglong2
    __shared__ __align__(16) float xs[16 * 4 * 32 * 4];   // 32 KB
    const int i0 = blockIdx.x * 16;
    const int b0 = blockIdx.y * 64;
    const int t  = threadIdx.x;

    const float4* xg = (const float4*)x;   // [256][1152][8] -> 2304 f4 per b
    for (int f = t; f < 2048; f += 320) {
        int b = f >> 5, q = f & 31;            // q = ii*2 + qe
        float4 v = xg[(size_t)(b0 + b) * 2304 + (size_t)i0 * 2 + q];
        int ii = q >> 1, qe = q & 1;
        int b2 = b >> 1, bl = b & 1;
        float* p = xs + (ii * 128 + qe * 64 + b2) * 4 + bl;
        p[0] = v.x; p[2] = v.y; p[128] = v.z; p[130] = v.w;
    }
    __syncthreads();

    const int jd2 = t % 80;          // j*8 + dp  (d0 = 2*dp)
    const int seg = t / 80;
    const int j   = jd2 >> 3, dp = jd2 & 7;
    const float4* Wg = (const float4*)W + (size_t)j * 36864 + dp * 4;
    __half2* uh2 = (__half2*)g_uhat;
    const ulonglong2* xq2base = (const ulonglong2*)xs;

    for (int bt = 0; bt < 2; bt++) {
        const int b2base = seg * 8 + bt * 4;
        u64t s0a[4] = {0,0,0,0};
        u64t s1a[4] = {0,0,0,0};
        for (int ii = 0; ii < 16; ii++) {
            const int i = i0 + ii;
            const float4 w00 = Wg[(size_t)i * 32];
            const float4 w01 = Wg[(size_t)i * 32 + 1];
            const float4 w10 = Wg[(size_t)i * 32 + 2];
            const float4 w11 = Wg[(size_t)i * 32 + 3];
            u64t wd0[8], wd1[8];
            wd0[0]=pack2(w00.x,w00.x); wd0[1]=pack2(w00.y,w00.y);
            wd0[2]=pack2(w00.z,w00.z); wd0[3]=pack2(w00.w,w00.w);
            wd0[4]=pack2(w01.x,w01.x); wd0[5]=pack2(w01.y,w01.y);
            wd0[6]=pack2(w01.z,w01.z); wd0[7]=pack2(w01.w,w01.w);
            wd1[0]=pack2(w10.x,w10.x); wd1[1]=pack2(w10.y,w10.y);
            wd1[2]=pack2(w10.z,w10.z); wd1[3]=pack2(w10.w,w10.w);
            wd1[4]=pack2(w11.x,w11.x); wd1[5]=pack2(w11.y,w11.y);
            wd1[6]=pack2(w11.z,w11.z); wd1[7]=pack2(w11.w,w11.w);
            const ulonglong2* xq2 = xq2base + ii * 128;
            #pragma unroll
            for (int bp = 0; bp < 4; bp++) {
                const int b2 = b2base + bp;
                u64t a0 = 0, a1 = 0;
                #pragma unroll
                for (int e2 = 0; e2 < 4; e2++) {
                    ulonglong2 xv = xq2[e2 * 32 + b2];
                    a0 = fma2(wd0[2*e2],   xv.x, a0);
                    a0 = fma2(wd0[2*e2+1], xv.y, a0);
                    a1 = fma2(wd1[2*e2],   xv.x, a1);
                    a1 = fma2(wd1[2*e2+1], xv.y, a1);
                }
                float u00,u01,u10,u11;
                unpack2(a0, u00, u01);   // d0 : b_even, b_odd
                unpack2(a1, u10, u11);   // d0+1
                const size_t bg = (size_t)(b0 + 2*b2);
                uh2[(bg       * ICAPS + i) * 80 + jd2] = __floats2half2_rn(u00, u10);
                uh2[((bg + 1) * ICAPS + i) * 80 + jd2] = __floats2half2_rn(u01, u11);
                s0a[bp] = addf2(s0a[bp], a0);
                s1a[bp] = addf2(s1a[bp], a1);
            }
        }
        #pragma unroll
        for (int bp = 0; bp < 4; bp++) {
            float p0,p1,q0,q1;
            unpack2(s0a[bp], p0, p1);
            unpack2(s1a[bp], q0, q1);
            float* sb = &g_acc[(b0 + 2*(b2base+bp)) * JD + jd2 * 2];
            atomicAdd(sb,           p0);
            atomicAdd(sb + 1,       q0);
            atomicAdd(sb + JD,      p1);
            atomicAdd(sb + JD + 1,  q1);
        }
    }
}

// -------- k_pass: routing pass, 3 pipelined chunks per CTA ---------------
// grid (6, 256), 320 threads. round = 1 or 2.
__global__ __launch_bounds__(320, 4) void k_pass(int round) {
    __shared__ __align__(16) __half su[2][CH * PADJD];   // 42 KB
    __shared__ float cc[CH * JN];    // logits / c ; reused as partials at end
    __shared__ float vs[JD];
    __shared__ float red[JD];
    __shared__ float sc[JN];

    const int b  = blockIdx.y;
    const int c0 = blockIdx.x * MCH;
    const int t  = threadIdx.x;
    const __half* ub = g_uhat + ((size_t)b * ICAPS + (size_t)c0 * CH) * JD;

    // ---- vs = v0 (+ v1 if round 2) ----
    if (t < JD) red[t] = 0.1f * g_acc[b * JD + t];
    __syncthreads();
    if (t < JN) {
        float sq = 0.f;
        #pragma unroll
        for (int d = 0; d < DN; d++) { float v = red[t*DN+d]; sq += v*v; }
        sc[t] = (sq / (1.0f + sq)) * rsqrtf(sq + 1e-7f);
    }
    __syncthreads();
    if (t < JD) vs[t] = red[t] * sc[t >> 4];
    if (round == 2) {
        __syncthreads();
        if (t < JD) red[t] = g_acc[(BATCH + b) * JD + t];
        __syncthreads();
        if (t < JN) {
            float sq = 0.f;
            #pragma unroll
            for (int d = 0; d < DN; d++) { float v = red[t*DN+d]; sq += v*v; }
            sc[t] = (sq / (1.0f + sq)) * rsqrtf(sq + 1e-7f);
        }
        __syncthreads();
        if (t < JD) vs[t] += red[t] * sc[t >> 4];
    }

    // ---- prefetch chunk 0 ----
    for (int f = t; f < CH * 20; f += 320) {
        int i = f / 20, q = f % 20;
        cp16(&su[0][i * PADJD + q * 8], ub + (size_t)i * JD + q * 8);
    }
    cp_commit();

    const int jd2 = t % 80;          // j*8+dp
    const int qq  = t / 80;          // i-quarter (16 i's)
    const int jB  = jd2 >> 3;
    float sa0 = 0.f, sa1 = 0.f;

    for (int c = 0; c < MCH; c++) {
        if (c + 1 < MCH) {
            const __half* src = ub + (size_t)(c + 1) * CH * JD;
            __half* dst = su[(c + 1) & 1];
            for (int f = t; f < CH * 20; f += 320) {
                int i = f / 20, q = f % 20;
                cp16(&dst[i * PADJD + q * 8], src + (size_t)i * JD + q * 8);
            }
            cp_commit();
            cp_wait<1>();
        } else {
            cp_wait<0>();
        }
        __syncthreads();
        const __half* u = su[c & 1];

        // ---- phase A: 640 (i,j) dot tasks ----
        #pragma unroll
        for (int k = 0; k < 2; k++) {
            int task = t + k * 320;
            int i = (task * 205) >> 11;          // floor(task/10)
            int j = task - i * 10;
            const __half2* up = (const __half2*)(u + i * PADJD + j * DN);
            const float2* v2 = (const float2*)(vs + j * DN);
            float a = 0.f;
            #pragma unroll
            for (int d2 = 0; d2 < 8; d2++) {
                float2 uf = __half22float2(up[d2]);
                float2 vv = v2[d2];
                a = fmaf(uf.x, vv.x, a);
                a = fmaf(uf.y, vv.y, a);
            }
            cc[i * JN + j] = a;
        }
        __syncthreads();

        // ---- softmax over j ----
        if (t < CH) {
            float l[JN];
            #pragma unroll
            for (int j = 0; j < JN; j++) l[j] = cc[t * JN + j];
            float m = l[0];
            #pragma unroll
            for (int j = 1; j < JN; j++) m = fmaxf(m, l[j]);
            float sum = 0.f;
            #pragma unroll
            for (int j = 0; j < JN; j++) { l[j] = __expf(l[j] - m); sum += l[j]; }
            float inv = __fdividef(1.0f, sum);
            #pragma unroll
            for (int j = 0; j < JN; j++) cc[t * JN + j] = l[j] * inv;
        }
        __syncthreads();

        // ---- phase B: per-quarter partial s over 16 i's ----
        {
            const __half2* uq = (const __half2*)u;   // row stride 84 half2
            const int ibase = qq * 16;
            #pragma unroll
            for (int k = 0; k < 16; k++) {
                const int i = ibase + k;
                const float cf = cc[i * JN + jB];
                float2 uf = __half22float2(uq[i * 84 + jd2]);
                sa0 = fmaf(uf.x, cf, sa0);
                sa1 = fmaf(uf.y, cf, sa1);
            }
        }
        __syncthreads();   // su[c&1] + cc reuse protection
    }

    // ---- cross-quarter reduce (reuse cc as [4][160]) + atomic ----
    cc[qq * JD + jd2 * 2]     = sa0;
    cc[qq * JD + jd2 * 2 + 1] = sa1;
    __syncthreads();
    if (t < JD) {
        float s = cc[t] + cc[JD + t] + cc[2*JD + t] + cc[3*JD + t];
        atomicAdd(&g_acc[(round * BATCH + b) * JD + t], s);
    }
}

// -------- k_final: out = squash(sacc2) ----------------------------------
__global__ void k_final(float* __restrict__ out) {
    __shared__ float red[JD];
    __shared__ float sc[JN];
    const int b = blockIdx.x, t = threadIdx.x;
    red[t] = g_acc[(2 * BATCH + b) * JD + t];
    __syncthreads();
    if (t < JN) {
        float sq = 0.f;
        #pragma unroll
        for (int d = 0; d < DN; d++) { float v = red[t*DN+d]; sq += v*v; }
        sc[t] = (sq / (1.0f + sq)) * rsqrtf(sq + 1e-7f);
    }
    __syncthreads();
    out[b * JD + t] = red[t] * sc[t >> 4];
}

// -------- launch --------------------------------------------------------
extern "C" void kernel_launch(void* const* d_in, const int* in_sizes, int n_in,
                              void* d_out, int out_size) {
    const float* x = (const float*)d_in[0];   // [256,1152,8]
    const float* W = (const float*)d_in[1];   // [10,1152,16,8]
    float* out = (float*)d_out;               // [256,10,16]

    void* acc_ptr = nullptr;
    cudaGetSymbolAddress(&acc_ptr, g_acc);
    cudaMemsetAsync(acc_ptr, 0, 3 * BATCH * JD * sizeof(float));

    k_uhat<<<dim3(ICAPS / 16, BATCH / 64), 320>>>(x, W);
    k_pass<<<dim3(GRIDX, BATCH), 320>>>(1);
    k_pass<<<dim3(GRIDX, BATCH), 320>>>(2);
    k_final<<<BATCH, JD>>>(out);
}

// round 6
// speedup vs baseline: 1.7484x; 1.0447x over previous
#include <cuda_runtime.h>
#include <cuda_fp16.h>
#include <math.h>

#define BATCH   256
#define JN      10
#define ICAPS   1152
#define DN      16
#define JD      160          // JN*DN
#define BT      32           // b per pass CTA
#define IT      32           // i per pass CTA
#define IB      4            // i batch (sync cadence)
#define NP      (ICAPS/IT)   // 36 partial slices

// -------- scratch ------------------------------------------------------
// u_hat layout: [j][i][b][16 x half]  (32B per (j,i,b) entry)
__device__ __half g_uhat[(size_t)JN * ICAPS * BATCH * DN];   // ~94.4 MB
__device__ float  g_acc[2 * BATCH * JD];                     // [0]=s0raw, [1]=s1
__device__ float  g_part[(size_t)NP * BATCH * JD];           // ~5.9 MB

// -------- f32x2 helpers (k_uhat) ----------------------------------------
typedef unsigned long long u64t;
__device__ __forceinline__ u64t pack2(float x, float y) {
    u64t r; asm("mov.b64 %0, {%1, %2};" : "=l"(r) : "f"(x), "f"(y)); return r;
}
__device__ __forceinline__ void unpack2(u64t v, float& x, float& y) {
    asm("mov.b64 {%0, %1}, %2;" : "=f"(x), "=f"(y) : "l"(v));
}
__device__ __forceinline__ u64t fma2(u64t a, u64t b, u64t c) {
    u64t d; asm("fma.rn.f32x2 %0, %1, %2, %3;" : "=l"(d) : "l"(a), "l"(b), "l"(c));
    return d;
}
__device__ __forceinline__ u64t addf2(u64t a, u64t b) {
    u64t d; asm("add.rn.f32x2 %0, %1, %2;" : "=l"(d) : "l"(a), "l"(b)); return d;
}

// -------- K1: u_hat = W @ x (fp16, [j][i][b] layout), fused partial s0 ---
// grid (72, 4), 320 threads: t%80 = jd2 (j*8+dp), t/80 = seg (16 b each)
__global__ __launch_bounds__(320, 2) void k_uhat(const float* __restrict__ x,
                                                 const float* __restrict__ W) {
    __shared__ __align__(16) float xs[16 * 4 * 32 * 4];   // 32 KB interleaved x
    const int i0 = blockIdx.x * 16;
    const int b0 = blockIdx.y * 64;
    const int t  = threadIdx.x;

    const float4* xg = (const float4*)x;   // [256][1152][8] -> 2304 f4 per b
    for (int f = t; f < 2048; f += 320) {
        int b = f >> 5, q = f & 31;            // q = ii*2 + qe
        float4 v = xg[(size_t)(b0 + b) * 2304 + (size_t)i0 * 2 + q];
        int ii = q >> 1, qe = q & 1;
        int b2 = b >> 1, bl = b & 1;
        float* p = xs + (ii * 128 + qe * 64 + b2) * 4 + bl;
        p[0] = v.x; p[2] = v.y; p[128] = v.z; p[130] = v.w;
    }
    __syncthreads();

    const int jd2 = t % 80;          // j*8 + dp  (d0 = 2*dp)
    const int seg = t / 80;
    const int j   = jd2 >> 3, dp = jd2 & 7;
    const float4* Wg = (const float4*)W + (size_t)j * 36864 + dp * 4;
    __half2* uh2 = (__half2*)g_uhat;
    const ulonglong2* xq2base = (const ulonglong2*)xs;

    for (int bt = 0; bt < 2; bt++) {
        const int b2base = seg * 8 + bt * 4;
        u64t s0a[4] = {0,0,0,0};
        u64t s1a[4] = {0,0,0,0};
        for (int ii = 0; ii < 16; ii++) {
            const int i = i0 + ii;
            const float4 w00 = Wg[(size_t)i * 32];
            const float4 w01 = Wg[(size_t)i * 32 + 1];
            const float4 w10 = Wg[(size_t)i * 32 + 2];
            const float4 w11 = Wg[(size_t)i * 32 + 3];
            u64t wd0[8], wd1[8];
            wd0[0]=pack2(w00.x,w00.x); wd0[1]=pack2(w00.y,w00.y);
            wd0[2]=pack2(w00.z,w00.z); wd0[3]=pack2(w00.w,w00.w);
            wd0[4]=pack2(w01.x,w01.x); wd0[5]=pack2(w01.y,w01.y);
            wd0[6]=pack2(w01.z,w01.z); wd0[7]=pack2(w01.w,w01.w);
            wd1[0]=pack2(w10.x,w10.x); wd1[1]=pack2(w10.y,w10.y);
            wd1[2]=pack2(w10.z,w10.z); wd1[3]=pack2(w10.w,w10.w);
            wd1[4]=pack2(w11.x,w11.x); wd1[5]=pack2(w11.y,w11.y);
            wd1[6]=pack2(w11.z,w11.z); wd1[7]=pack2(w11.w,w11.w);
            const ulonglong2* xq2 = xq2base + ii * 128;
            const size_t obase = ((size_t)j * ICAPS + i) * BATCH;
            #pragma unroll
            for (int bp = 0; bp < 4; bp++) {
                const int b2 = b2base + bp;
                u64t a0 = 0, a1 = 0;
                #pragma unroll
                for (int e2 = 0; e2 < 4; e2++) {
                    ulonglong2 xv = xq2[e2 * 32 + b2];
                    a0 = fma2(wd0[2*e2],   xv.x, a0);
                    a0 = fma2(wd0[2*e2+1], xv.y, a0);
                    a1 = fma2(wd1[2*e2],   xv.x, a1);
                    a1 = fma2(wd1[2*e2+1], xv.y, a1);
                }
                float u00,u01,u10,u11;
                unpack2(a0, u00, u01);   // d0   : b_even, b_odd
                unpack2(a1, u10, u11);   // d0+1 : b_even, b_odd
                const int bg = b0 + 2*b2;
                uh2[(obase + bg)     * 8 + dp] = __floats2half2_rn(u00, u10);
                uh2[(obase + bg + 1) * 8 + dp] = __floats2half2_rn(u01, u11);
                s0a[bp] = addf2(s0a[bp], a0);
                s1a[bp] = addf2(s1a[bp], a1);
            }
        }
        #pragma unroll
        for (int bp = 0; bp < 4; bp++) {
            float p0,p1,q0,q1;
            unpack2(s0a[bp], p0, p1);
            unpack2(s1a[bp], q0, q1);
            float* sb = &g_acc[(b0 + 2*(b2base+bp)) * JD + jd2 * 2];
            atomicAdd(sb,           p0);
            atomicAdd(sb + 1,       q0);
            atomicAdd(sb + JD,      p1);
            atomicAdd(sb + JD + 1,  q1);
        }
    }
}

// -------- k_pass: register-resident routing pass -------------------------
// grid (36 i-tiles, 8 b-tiles), block (32 b, 10 j). round = 1 or 2.
// Writes per-CTA s partials to g_part (no atomics).
__global__ __launch_bounds__(320, 3) void k_pass(int round) {
    __shared__ float se[2][IB][JN][BT];   // e-values, 10 KB

    const int lane = threadIdx.x;          // b within tile
    const int j    = threadIdx.y;
    const int b    = blockIdx.y * BT + lane;
    const int i0   = blockIdx.x * IT;

    // ---- vs[j,:] = v0 (+ v1) in registers ----
    float vs[DN];
    {
        float tmp[DN]; float sq = 0.f;
        const float* a0 = g_acc + b * JD + j * DN;
        #pragma unroll
        for (int d = 0; d < DN; d++) { tmp[d] = 0.1f * a0[d]; sq += tmp[d]*tmp[d]; }
        float sc = (sq / (1.0f + sq)) * rsqrtf(sq + 1e-7f);
        #pragma unroll
        for (int d = 0; d < DN; d++) vs[d] = tmp[d] * sc;
        if (round == 2) {
            const float* a1 = g_acc + BATCH * JD + b * JD + j * DN;
            sq = 0.f;
            #pragma unroll
            for (int d = 0; d < DN; d++) { tmp[d] = a1[d]; sq += tmp[d]*tmp[d]; }
            sc = (sq / (1.0f + sq)) * rsqrtf(sq + 1e-7f);
            #pragma unroll
            for (int d = 0; d < DN; d++) vs[d] += tmp[d] * sc;
        }
    }

    const uint4* ug = (const uint4*)g_uhat;
    // entry (j,i,b) occupies 32B = 2 uint4; uint4 index = 2*entry
    const size_t e0 = (((size_t)j * ICAPS + i0) * BATCH + b) * 2;

    float s[DN];
    #pragma unroll
    for (int d = 0; d < DN; d++) s[d] = 0.f;

    int buf = 0;
    for (int t0 = 0; t0 < IT; t0 += IB) {
        // ---- phase A: load, dot, exp, publish e ----
        float ev[IB];
        #pragma unroll
        for (int k = 0; k < IB; k++) {
            const size_t ix = e0 + (size_t)(t0 + k) * (2 * BATCH);
            uint4 lo = ug[ix];
            uint4 hi = ug[ix + 1];
            const __half2* h0 = (const __half2*)&lo;
            const __half2* h1 = (const __half2*)&hi;
            float a = 0.f;
            #pragma unroll
            for (int d2 = 0; d2 < 4; d2++) {
                float2 f0 = __half22float2(h0[d2]);
                a = fmaf(f0.x, vs[2*d2],     a);
                a = fmaf(f0.y, vs[2*d2 + 1], a);
                float2 f1 = __half22float2(h1[d2]);
                a = fmaf(f1.x, vs[8 + 2*d2], a);
                a = fmaf(f1.y, vs[9 + 2*d2], a);
            }
            ev[k] = __expf(a);
            se[buf][k][j][lane] = ev[k];
        }
        __syncthreads();
        // ---- phase B: normalize + accumulate (reload = L1 hit) ----
        #pragma unroll
        for (int k = 0; k < IB; k++) {
            float sum = 0.f;
            #pragma unroll
            for (int jj = 0; jj < JN; jj++) sum += se[buf][k][jj][lane];
            float c = __fdividef(ev[k], sum);
            const size_t ix = e0 + (size_t)(t0 + k) * (2 * BATCH);
            uint4 lo = ug[ix];
            uint4 hi = ug[ix + 1];
            const __half2* h0 = (const __half2*)&lo;
            const __half2* h1 = (const __half2*)&hi;
            #pragma unroll
            for (int d2 = 0; d2 < 4; d2++) {
                float2 f0 = __half22float2(h0[d2]);
                s[2*d2]     = fmaf(f0.x, c, s[2*d2]);
                s[2*d2 + 1] = fmaf(f0.y, c, s[2*d2 + 1]);
                float2 f1 = __half22float2(h1[d2]);
                s[8 + 2*d2] = fmaf(f1.x, c, s[8 + 2*d2]);
                s[9 + 2*d2] = fmaf(f1.y, c, s[9 + 2*d2]);
            }
        }
        buf ^= 1;
    }

    // ---- write per-CTA partial (coalesced float4 stores) ----
    float* dst = g_part + (size_t)blockIdx.x * (BATCH * JD)
               + (size_t)b * JD + j * DN;
    #pragma unroll
    for (int q = 0; q < 4; q++)
        ((float4*)dst)[q] = make_float4(s[4*q], s[4*q+1], s[4*q+2], s[4*q+3]);
}

// -------- k_reduce: s1 = sum of partials --------------------------------
__global__ void k_reduce() {
    const int idx = blockIdx.x * 256 + threadIdx.x;   // < BATCH*JD
    float s = 0.f;
    #pragma unroll 4
    for (int p = 0; p < NP; p++) s += g_part[(size_t)p * (BATCH * JD) + idx];
    g_acc[BATCH * JD + idx] = s;
}

// -------- k_final: out = squash(sum of partials) -------------------------
__global__ __launch_bounds__(1024) void k_final(float* __restrict__ out) {
    const int idx = blockIdx.x * 1024 + threadIdx.x;   // b*160 + jd
    float v = 0.f;
    #pragma unroll 4
    for (int p = 0; p < NP; p++) v += g_part[(size_t)p * (BATCH * JD) + idx];
    float sq = v * v;
    sq += __shfl_xor_sync(0xffffffff, sq, 1);
    sq += __shfl_xor_sync(0xffffffff, sq, 2);
    sq += __shfl_xor_sync(0xffffffff, sq, 4);
    sq += __shfl_xor_sync(0xffffffff, sq, 8);
    float sc = (sq / (1.0f + sq)) * rsqrtf(sq + 1e-7f);
    out[idx] = v * sc;
}

// -------- launch --------------------------------------------------------
extern "C" void kernel_launch(void* const* d_in, const int* in_sizes, int n_in,
                              void* d_out, int out_size) {
    const float* x = (const float*)d_in[0];   // [256,1152,8]
    const float* W = (const float*)d_in[1];   // [10,1152,16,8]
    float* out = (float*)d_out;               // [256,10,16]

    void* acc_ptr = nullptr;
    cudaGetSymbolAddress(&acc_ptr, g_acc);
    cudaMemsetAsync(acc_ptr, 0, BATCH * JD * sizeof(float));   // s0 only

    k_uhat<<<dim3(ICAPS / 16, BATCH / 64), 320>>>(x, W);
    k_pass<<<dim3(NP, BATCH / BT), dim3(BT, JN)>>>(1);
    k_reduce<<<BATCH * JD / 256, 256>>>();
    k_pass<<<dim3(NP, BATCH / BT), dim3(BT, JN)>>>(2);
    k_final<<<BATCH * JD / 1024, 1024>>>(out);
}